// round 3
// baseline (speedup 1.0000x reference)
#include <cuda_runtime.h>

#define DD   400
#define LC   2048
#define LA   512
#define NB   64

#define BM 128
#define BN 128
#define BK 16

// Scratch for the rank-1 epilogue terms (allocation-free rule -> device globals)
__device__ float g_ctx_term[NB * LC];   // 512 KB
__device__ float g_asp_term[NB * LA];   // 128 KB

// One warp per row: out[row] = dot(x[row, 0:400], w[0:400])
__global__ void row_dot_kernel(const float* __restrict__ x,
                               const float* __restrict__ w,
                               float* __restrict__ out, int nrows)
{
    int gwarp = (blockIdx.x * blockDim.x + threadIdx.x) >> 5;
    int lane  = threadIdx.x & 31;
    if (gwarp >= nrows) return;

    const float4* row = reinterpret_cast<const float4*>(x + (size_t)gwarp * DD);
    const float4* w4  = reinterpret_cast<const float4*>(w);
    float s = 0.f;
    #pragma unroll 4
    for (int c = lane; c < DD / 4; c += 32) {
        float4 a = row[c];
        float4 b = __ldg(&w4[c]);
        s += a.x * b.x + a.y * b.y + a.z * b.z + a.w * b.w;
    }
    #pragma unroll
    for (int off = 16; off; off >>= 1) s += __shfl_xor_sync(0xffffffffu, s, off);
    if (lane == 0) out[gwarp] = s;
}

// C[b, i, j] = sum_d (ctx[b,i,d]*w3[d]) * asp[b,j,d] + ctx_term[b,i] + asp_term[b,j]
__global__ __launch_bounds__(256, 2)
void gemm_epilogue_kernel(const float* __restrict__ ctx,
                          const float* __restrict__ asp,
                          const float* __restrict__ w_u,
                          float* __restrict__ out)
{
    __shared__ float As[BK][BM];   // transposed A tile (k-major)
    __shared__ float Bs[BK][BN];   // transposed B tile
    __shared__ float w3s[DD];

    const int tid = threadIdx.x;
    const int b   = blockIdx.z;
    const int rowTile = blockIdx.y * BM;
    const int colTile = blockIdx.x * BN;

    const float* Ag = ctx + (size_t)b * LC * DD + (size_t)rowTile * DD;
    const float* Bg = asp + (size_t)b * LA * DD + (size_t)colTile * DD;
    float*       Cg = out + (size_t)b * LC * LA + (size_t)rowTile * LA + colTile;

    for (int i = tid; i < DD; i += 256) w3s[i] = w_u[2 * DD + i];
    __syncthreads();

    const int lrow = tid >> 2;          // 0..63
    const int lc4  = (tid & 3) * 4;     // 0,4,8,12

    const int tx = tid & 15;            // 16 col groups of 8
    const int ty = tid >> 4;            // 16 row groups of 8

    float acc[8][8];
    #pragma unroll
    for (int m = 0; m < 8; m++)
        #pragma unroll
        for (int n = 0; n < 8; n++) acc[m][n] = 0.f;

    for (int k0 = 0; k0 < DD; k0 += BK) {
        // --- load tiles (each thread: 2 float4 of A, 2 float4 of B) ---
        #pragma unroll
        for (int p = 0; p < 2; p++) {
            int r = lrow + p * 64;
            float4 v = *reinterpret_cast<const float4*>(Ag + (size_t)r * DD + k0 + lc4);
            As[lc4 + 0][r] = v.x * w3s[k0 + lc4 + 0];
            As[lc4 + 1][r] = v.y * w3s[k0 + lc4 + 1];
            As[lc4 + 2][r] = v.z * w3s[k0 + lc4 + 2];
            As[lc4 + 3][r] = v.w * w3s[k0 + lc4 + 3];

            float4 u = *reinterpret_cast<const float4*>(Bg + (size_t)r * DD + k0 + lc4);
            Bs[lc4 + 0][r] = u.x;
            Bs[lc4 + 1][r] = u.y;
            Bs[lc4 + 2][r] = u.z;
            Bs[lc4 + 3][r] = u.w;
        }
        __syncthreads();

        // --- compute ---
        #pragma unroll
        for (int k = 0; k < BK; k++) {
            float a[8], bb[8];
            *reinterpret_cast<float4*>(&a[0])  = *reinterpret_cast<const float4*>(&As[k][ty * 8]);
            *reinterpret_cast<float4*>(&a[4])  = *reinterpret_cast<const float4*>(&As[k][ty * 8 + 4]);
            *reinterpret_cast<float4*>(&bb[0]) = *reinterpret_cast<const float4*>(&Bs[k][tx * 8]);
            *reinterpret_cast<float4*>(&bb[4]) = *reinterpret_cast<const float4*>(&Bs[k][tx * 8 + 4]);
            #pragma unroll
            for (int m = 0; m < 8; m++)
                #pragma unroll
                for (int n = 0; n < 8; n++)
                    acc[m][n] += a[m] * bb[n];
        }
        __syncthreads();
    }

    // --- epilogue: add ctx_term (per row) + asp_term (per col), store float4 ---
    const float* rterm = g_ctx_term + b * LC + rowTile;
    const float* cterm = g_asp_term + b * LA + colTile;

    float ct[8];
    #pragma unroll
    for (int n = 0; n < 8; n++) ct[n] = cterm[tx * 8 + n];

    #pragma unroll
    for (int m = 0; m < 8; m++) {
        float rt = rterm[ty * 8 + m];
        float4 o0, o1;
        o0.x = acc[m][0] + rt + ct[0];
        o0.y = acc[m][1] + rt + ct[1];
        o0.z = acc[m][2] + rt + ct[2];
        o0.w = acc[m][3] + rt + ct[3];
        o1.x = acc[m][4] + rt + ct[4];
        o1.y = acc[m][5] + rt + ct[5];
        o1.z = acc[m][6] + rt + ct[6];
        o1.w = acc[m][7] + rt + ct[7];
        float* crow = Cg + (size_t)(ty * 8 + m) * LA + tx * 8;
        *reinterpret_cast<float4*>(crow)     = o0;
        *reinterpret_cast<float4*>(crow + 4) = o1;
    }
}

extern "C" void kernel_launch(void* const* d_in, const int* in_sizes, int n_in,
                              void* d_out, int out_size)
{
    // Resolve inputs by element count (robust to metadata ordering):
    // ctx: 64*2048*400 = 52428800, asp: 64*512*400 = 13107200, w_u: 1200
    const float* ctx = nullptr;
    const float* asp = nullptr;
    const float* w_u = nullptr;
    for (int i = 0; i < n_in; i++) {
        if (in_sizes[i] == NB * LC * DD)      ctx = (const float*)d_in[i];
        else if (in_sizes[i] == NB * LA * DD) asp = (const float*)d_in[i];
        else if (in_sizes[i] == 3 * DD)       w_u = (const float*)d_in[i];
    }
    float* out = (float*)d_out;

    float* ctx_term = nullptr;
    float* asp_term = nullptr;
    cudaGetSymbolAddress((void**)&ctx_term, g_ctx_term);
    cudaGetSymbolAddress((void**)&asp_term, g_asp_term);

    // Row-term kernels: one warp per row, 8 warps per block.
    {
        int nrows = NB * LC;                     // 131072
        row_dot_kernel<<<nrows / 8, 256>>>(ctx, w_u, ctx_term, nrows);
    }
    {
        int nrows = NB * LA;                     // 32768
        row_dot_kernel<<<nrows / 8, 256>>>(asp, w_u + DD, asp_term, nrows);
    }

    // Main GEMM + epilogue.
    dim3 grid(LA / BN, LC / BM, NB);             // (4, 16, 64)
    gemm_epilogue_kernel<<<grid, 256>>>(ctx, asp, w_u, out);

    (void)out_size;
}

// round 6
// speedup vs baseline: 1.5752x; 1.5752x over previous
#include <cuda_runtime.h>
#include <cuda_bf16.h>
#include <cstdint>

#define DD 400
#define LC 2048
#define LA 512
#define NB 64

#define BM 128
#define BN 64
#define BK 32
#define NCH 13            // ceil(400/32) -> K padded to 416
#define KPAD 416

// smem layout (bytes). bf16 tiles with 80B row stride (64B data + 16B pad)
#define ROWB 80
#define A_TILE (BM * ROWB)          // 10240
#define B_TILE (BN * ROWB)          // 5120
#define STAGE  (2 * A_TILE + 2 * B_TILE)   // 30720: Ahi, Alo, Bhi, Blo
#define OFF_AHI 0
#define OFF_ALO A_TILE
#define OFF_BHI (2 * A_TILE)
#define OFF_BLO (2 * A_TILE + B_TILE)
#define W_OFF   (2 * STAGE)                 // 61440
#define W_BYTES (KPAD * 4)                  // 1664 per vector
#define RT_OFF  (W_OFF + 3 * W_BYTES)       // 66432, 128 floats
#define CT_OFF  (RT_OFF + 512)              // 66944, 64 floats
#define SMEM_TOTAL (CT_OFF + 256)           // 67200

__device__ __forceinline__ uint32_t smem_u32(const void* p) {
    uint32_t a;
    asm("{ .reg .u64 t; cvta.to.shared.u64 t, %1; cvt.u32.u64 %0, t; }" : "=r"(a) : "l"(p));
    return a;
}

__device__ __forceinline__ void ldsm_x4(uint32_t& r0, uint32_t& r1, uint32_t& r2, uint32_t& r3,
                                        uint32_t addr) {
    asm volatile("ldmatrix.sync.aligned.m8n8.x4.shared.b16 {%0,%1,%2,%3}, [%4];"
                 : "=r"(r0), "=r"(r1), "=r"(r2), "=r"(r3) : "r"(addr));
}

__device__ __forceinline__ void mma_bf16(float* d, const uint32_t* a, uint32_t b0, uint32_t b1) {
    asm volatile(
        "mma.sync.aligned.m16n8k16.row.col.f32.bf16.bf16.f32 "
        "{%0,%1,%2,%3}, {%4,%5,%6,%7}, {%8,%9}, {%0,%1,%2,%3};"
        : "+f"(d[0]), "+f"(d[1]), "+f"(d[2]), "+f"(d[3])
        : "r"(a[0]), "r"(a[1]), "r"(a[2]), "r"(a[3]), "r"(b0), "r"(b1));
}

__device__ __forceinline__ uint32_t packbf(float a, float b) {
    __nv_bfloat162 h = __floats2bfloat162_rn(a, b);
    return *reinterpret_cast<uint32_t*>(&h);
}

// split 8 floats into bf16 hi (uint4) and bf16 lo (uint4)
__device__ __forceinline__ void split8(const float* f, uint4& hi, uint4& lo) {
    float h[8], l[8];
    #pragma unroll
    for (int j = 0; j < 8; j++) {
        h[j] = __bfloat162float(__float2bfloat16(f[j]));
        l[j] = f[j] - h[j];
    }
    hi = make_uint4(packbf(h[0], h[1]), packbf(h[2], h[3]), packbf(h[4], h[5]), packbf(h[6], h[7]));
    lo = make_uint4(packbf(l[0], l[1]), packbf(l[2], l[3]), packbf(l[4], l[5]), packbf(l[6], l[7]));
}

__global__ __launch_bounds__(256, 2)
void alignment_hmma_kernel(const float* __restrict__ ctx,
                           const float* __restrict__ asp,
                           const float* __restrict__ w_u,
                           float* __restrict__ out)
{
    extern __shared__ char sm[];
    const uint32_t smu = smem_u32(sm);

    const int tid  = threadIdx.x;
    const int w    = tid >> 5;
    const int lane = tid & 31;
    const int b    = blockIdx.z;
    const int rowTile = blockIdx.y * BM;
    const int colTile = blockIdx.x * BN;

    const float* Ag = ctx + (size_t)b * LC * DD + (size_t)rowTile * DD;
    const float* Bg = asp + (size_t)b * LA * DD + (size_t)colTile * DD;

    float* w1s = (float*)(sm + W_OFF);
    float* w2s = (float*)(sm + W_OFF + W_BYTES);
    float* w3s = (float*)(sm + W_OFF + 2 * W_BYTES);
    float* rt_s = (float*)(sm + RT_OFF);
    float* ct_s = (float*)(sm + CT_OFF);

    for (int i = tid; i < KPAD; i += 256) {
        bool v = i < DD;
        w1s[i] = v ? w_u[i]          : 0.f;
        w2s[i] = v ? w_u[DD + i]     : 0.f;
        w3s[i] = v ? w_u[2 * DD + i] : 0.f;
    }
    __syncthreads();

    // loader roles
    const int arow = tid >> 1;          // 0..127
    const int ahalf = tid & 1;          // 16 k-elems each
    const int brow = tid >> 2;          // 0..63
    const int bq   = tid & 3;           // 8 k-elems each
    const uint32_t aswz = ((uint32_t)(arow >> 3) & 1u) << 1;   // XOR on group idx
    const uint32_t bswz = ((uint32_t)(brow >> 3) & 1u) << 1;

    float rt_acc = 0.f, ct_acc = 0.f;

    float4 nA[4], nB[2];

    // ---- load chunk 0 ----
    {
        const int k0 = 0;
        #pragma unroll
        for (int i = 0; i < 4; i++) {
            int k = k0 + ahalf * 16 + i * 4;
            nA[i] = (k < DD) ? __ldg((const float4*)(Ag + (size_t)arow * DD + k))
                             : make_float4(0.f, 0.f, 0.f, 0.f);
        }
        #pragma unroll
        for (int i = 0; i < 2; i++) {
            int k = k0 + bq * 8 + i * 4;
            nB[i] = (k < DD) ? __ldg((const float4*)(Bg + (size_t)brow * DD + k))
                             : make_float4(0.f, 0.f, 0.f, 0.f);
        }
    }

    // mma thread geometry
    const int warpMoff = (w & 1) * 64;
    const int warpNoff = (w >> 1) * 16;
    const int lr  = lane & 15;
    const int lkg = lane >> 4;

    float acc[4][2][4];
    #pragma unroll
    for (int mf = 0; mf < 4; mf++)
        #pragma unroll
        for (int nf = 0; nf < 2; nf++)
            #pragma unroll
            for (int i = 0; i < 4; i++) acc[mf][nf][i] = 0.f;

    // convert+store helper is inlined twice via lambda
    auto convert_store = [&](int c) {
        char* st = sm + (c & 1) * STAGE;
        const int k0 = c * BK;
        // A: fold w3, accumulate rt with w1
        #pragma unroll
        for (int g = 0; g < 2; g++) {
            float f[8];
            f[0] = nA[2 * g].x; f[1] = nA[2 * g].y; f[2] = nA[2 * g].z; f[3] = nA[2 * g].w;
            f[4] = nA[2 * g + 1].x; f[5] = nA[2 * g + 1].y; f[6] = nA[2 * g + 1].z; f[7] = nA[2 * g + 1].w;
            const int kb = k0 + ahalf * 16 + g * 8;
            #pragma unroll
            for (int j = 0; j < 8; j++) {
                rt_acc += f[j] * w1s[kb + j];
                f[j] *= w3s[kb + j];
            }
            uint4 hi, lo;
            split8(f, hi, lo);
            const uint32_t gg = ((uint32_t)(ahalf * 2 + g)) ^ aswz;
            *(uint4*)(st + OFF_AHI + arow * ROWB + gg * 16) = hi;
            *(uint4*)(st + OFF_ALO + arow * ROWB + gg * 16) = lo;
        }
        // B: accumulate ct with w2
        {
            float f[8];
            f[0] = nB[0].x; f[1] = nB[0].y; f[2] = nB[0].z; f[3] = nB[0].w;
            f[4] = nB[1].x; f[5] = nB[1].y; f[6] = nB[1].z; f[7] = nB[1].w;
            const int kb = k0 + bq * 8;
            #pragma unroll
            for (int j = 0; j < 8; j++) ct_acc += f[j] * w2s[kb + j];
            uint4 hi, lo;
            split8(f, hi, lo);
            const uint32_t gg = ((uint32_t)bq) ^ bswz;
            *(uint4*)(st + OFF_BHI + brow * ROWB + gg * 16) = hi;
            *(uint4*)(st + OFF_BLO + brow * ROWB + gg * 16) = lo;
        }
    };

    convert_store(0);
    __syncthreads();

    for (int c = 0; c < NCH; c++) {
        // prefetch chunk c+1 from global
        if (c + 1 < NCH) {
            const int k0 = (c + 1) * BK;
            #pragma unroll
            for (int i = 0; i < 4; i++) {
                int k = k0 + ahalf * 16 + i * 4;
                nA[i] = (k < DD) ? __ldg((const float4*)(Ag + (size_t)arow * DD + k))
                                 : make_float4(0.f, 0.f, 0.f, 0.f);
            }
            #pragma unroll
            for (int i = 0; i < 2; i++) {
                int k = k0 + bq * 8 + i * 4;
                nB[i] = (k < DD) ? __ldg((const float4*)(Bg + (size_t)brow * DD + k))
                                 : make_float4(0.f, 0.f, 0.f, 0.f);
            }
        }

        // ---- MMA over chunk c ----
        {
            const uint32_t st = smu + (uint32_t)(c & 1) * STAGE;
            #pragma unroll
            for (int ks = 0; ks < 2; ks++) {
                uint32_t ah[4][4], al[4][4], bh[4], bl[4];
                #pragma unroll
                for (int mf = 0; mf < 4; mf++) {
                    const int row = warpMoff + mf * 16 + lr;
                    const uint32_t kg = ((uint32_t)(ks * 2 + lkg)) ^ ((((uint32_t)row >> 3) & 1u) << 1);
                    const uint32_t off = (uint32_t)row * ROWB + kg * 16;
                    ldsm_x4(ah[mf][0], ah[mf][1], ah[mf][2], ah[mf][3], st + OFF_AHI + off);
                    ldsm_x4(al[mf][0], al[mf][1], al[mf][2], al[mf][3], st + OFF_ALO + off);
                }
                {
                    const int row = warpNoff + lr;
                    const uint32_t kg = ((uint32_t)(ks * 2 + lkg)) ^ ((((uint32_t)row >> 3) & 1u) << 1);
                    const uint32_t off = (uint32_t)row * ROWB + kg * 16;
                    ldsm_x4(bh[0], bh[1], bh[2], bh[3], st + OFF_BHI + off);
                    ldsm_x4(bl[0], bl[1], bl[2], bl[3], st + OFF_BLO + off);
                }
                #pragma unroll
                for (int mf = 0; mf < 4; mf++) {
                    // nf=0 uses B regs (0,2); nf=1 uses (1,3)
                    mma_bf16(acc[mf][0], ah[mf], bh[0], bh[2]);
                    mma_bf16(acc[mf][0], ah[mf], bl[0], bl[2]);
                    mma_bf16(acc[mf][0], al[mf], bh[0], bh[2]);
                    mma_bf16(acc[mf][1], ah[mf], bh[1], bh[3]);
                    mma_bf16(acc[mf][1], ah[mf], bl[1], bl[3]);
                    mma_bf16(acc[mf][1], al[mf], bh[1], bh[3]);
                }
            }
        }

        if (c + 1 < NCH) convert_store(c + 1);
        __syncthreads();
    }

    // ---- reduce rank-1 terms ----
    {
        float r = rt_acc + __shfl_xor_sync(0xffffffffu, rt_acc, 1);
        if (ahalf == 0) rt_s[arow] = r;
        float cte = ct_acc + __shfl_xor_sync(0xffffffffu, ct_acc, 1);
        cte += __shfl_xor_sync(0xffffffffu, cte, 2);
        if (bq == 0) ct_s[brow] = cte;
    }
    __syncthreads();

    // ---- epilogue ----
    float* Cg = out + ((size_t)b * LC + rowTile) * LA + colTile;
    #pragma unroll
    for (int mf = 0; mf < 4; mf++) {
        const int r0 = warpMoff + mf * 16 + (lane >> 2);
        const int r1 = r0 + 8;
        const float rt0 = rt_s[r0], rt1 = rt_s[r1];
        #pragma unroll
        for (int nf = 0; nf < 2; nf++) {
            const int c0 = warpNoff + nf * 8 + (lane & 3) * 2;
            const float ct0 = ct_s[c0], ct1 = ct_s[c0 + 1];
            float2 v0 = make_float2(acc[mf][nf][0] + rt0 + ct0, acc[mf][nf][1] + rt0 + ct1);
            float2 v1 = make_float2(acc[mf][nf][2] + rt1 + ct0, acc[mf][nf][3] + rt1 + ct1);
            *(float2*)(Cg + (size_t)r0 * LA + c0) = v0;
            *(float2*)(Cg + (size_t)r1 * LA + c0) = v1;
        }
    }
}

extern "C" void kernel_launch(void* const* d_in, const int* in_sizes, int n_in,
                              void* d_out, int out_size)
{
    const float* ctx = nullptr;
    const float* asp = nullptr;
    const float* w_u = nullptr;
    for (int i = 0; i < n_in; i++) {
        if (in_sizes[i] == NB * LC * DD)      ctx = (const float*)d_in[i];
        else if (in_sizes[i] == NB * LA * DD) asp = (const float*)d_in[i];
        else if (in_sizes[i] == 3 * DD)       w_u = (const float*)d_in[i];
    }
    float* out = (float*)d_out;

    cudaFuncSetAttribute(alignment_hmma_kernel,
                         cudaFuncAttributeMaxDynamicSharedMemorySize, SMEM_TOTAL);

    dim3 grid(LA / BN, LC / BM, NB);   // (8, 16, 64)
    alignment_hmma_kernel<<<grid, 256, SMEM_TOTAL>>>(ctx, asp, w_u, out);

    (void)out_size;
}

// round 7
// speedup vs baseline: 1.7411x; 1.1053x over previous
#include <cuda_runtime.h>
#include <cuda_bf16.h>
#include <cstdint>

#define DD 400
#define LC 2048
#define LA 512
#define NB 64

#define BM 128
#define BN 128
#define BK 32
#define NCH 13            // ceil(400/32) -> K padded to 416
#define KPAD 416

// smem layout (bytes). bf16 tiles with 80B row stride (64B data + 16B pad)
#define ROWB 80
#define A_TILE (BM * ROWB)          // 10240
#define B_TILE (BN * ROWB)          // 10240
#define STAGE  (2 * A_TILE + 2 * B_TILE)   // 40960: Ahi, Alo, Bhi, Blo
#define OFF_AHI 0
#define OFF_ALO A_TILE
#define OFF_BHI (2 * A_TILE)
#define OFF_BLO (2 * A_TILE + B_TILE)
#define W_OFF   (2 * STAGE)                 // 81920
#define W_BYTES (KPAD * 4)                  // 1664 per vector
#define RT_OFF  (W_OFF + 3 * W_BYTES)       // 128 floats
#define CT_OFF  (RT_OFF + 512)              // 128 floats
#define SMEM_TOTAL (CT_OFF + 512)

__device__ __forceinline__ uint32_t smem_u32(const void* p) {
    uint32_t a;
    asm("{ .reg .u64 t; cvta.to.shared.u64 t, %1; cvt.u32.u64 %0, t; }" : "=r"(a) : "l"(p));
    return a;
}

__device__ __forceinline__ void ldsm_x4(uint32_t& r0, uint32_t& r1, uint32_t& r2, uint32_t& r3,
                                        uint32_t addr) {
    asm volatile("ldmatrix.sync.aligned.m8n8.x4.shared.b16 {%0,%1,%2,%3}, [%4];"
                 : "=r"(r0), "=r"(r1), "=r"(r2), "=r"(r3) : "r"(addr));
}

__device__ __forceinline__ void mma_bf16(float* d, const uint32_t* a, uint32_t b0, uint32_t b1) {
    asm volatile(
        "mma.sync.aligned.m16n8k16.row.col.f32.bf16.bf16.f32 "
        "{%0,%1,%2,%3}, {%4,%5,%6,%7}, {%8,%9}, {%0,%1,%2,%3};"
        : "+f"(d[0]), "+f"(d[1]), "+f"(d[2]), "+f"(d[3])
        : "r"(a[0]), "r"(a[1]), "r"(a[2]), "r"(a[3]), "r"(b0), "r"(b1));
}

__device__ __forceinline__ uint32_t packbf(float a, float b) {
    __nv_bfloat162 h = __floats2bfloat162_rn(a, b);
    return *reinterpret_cast<uint32_t*>(&h);
}

// split 8 floats into bf16 hi (uint4) and bf16 lo (uint4)
__device__ __forceinline__ void split8(const float* f, uint4& hi, uint4& lo) {
    float h[8], l[8];
    #pragma unroll
    for (int j = 0; j < 8; j++) {
        h[j] = __bfloat162float(__float2bfloat16(f[j]));
        l[j] = f[j] - h[j];
    }
    hi = make_uint4(packbf(h[0], h[1]), packbf(h[2], h[3]), packbf(h[4], h[5]), packbf(h[6], h[7]));
    lo = make_uint4(packbf(l[0], l[1]), packbf(l[2], l[3]), packbf(l[4], l[5]), packbf(l[6], l[7]));
}

__global__ __launch_bounds__(256, 1)
void alignment_hmma_kernel(const float* __restrict__ ctx,
                           const float* __restrict__ asp,
                           const float* __restrict__ w_u,
                           float* __restrict__ out)
{
    extern __shared__ char sm[];
    const uint32_t smu = smem_u32(sm);

    const int tid  = threadIdx.x;
    const int w    = tid >> 5;
    const int lane = tid & 31;
    const int b    = blockIdx.z;
    const int rowTile = blockIdx.y * BM;
    const int colTile = blockIdx.x * BN;

    const float* Ag = ctx + (size_t)b * LC * DD + (size_t)rowTile * DD;
    const float* Bg = asp + (size_t)b * LA * DD + (size_t)colTile * DD;

    float* w1s = (float*)(sm + W_OFF);
    float* w2s = (float*)(sm + W_OFF + W_BYTES);
    float* w3s = (float*)(sm + W_OFF + 2 * W_BYTES);
    float* rt_s = (float*)(sm + RT_OFF);
    float* ct_s = (float*)(sm + CT_OFF);

    for (int i = tid; i < KPAD; i += 256) {
        bool v = i < DD;
        w1s[i] = v ? w_u[i]          : 0.f;
        w2s[i] = v ? w_u[DD + i]     : 0.f;
        w3s[i] = v ? w_u[2 * DD + i] : 0.f;
    }
    __syncthreads();

    // loader roles: symmetric for A and B (128 rows each)
    const int lrow  = tid >> 1;         // 0..127
    const int lhalf = tid & 1;          // which 16 k-elems
    const uint32_t lswz = ((uint32_t)(lrow >> 3) & 1u) << 1;   // XOR on 16B-group idx

    float rt_acc = 0.f, ct_acc = 0.f;

    float4 nA[4], nB[4];

    auto prefetch = [&](int c) {
        const int k0 = c * BK;
        #pragma unroll
        for (int i = 0; i < 4; i++) {
            int k = k0 + lhalf * 16 + i * 4;
            bool kv = k < DD;
            nA[i] = kv ? __ldg((const float4*)(Ag + (size_t)lrow * DD + k))
                       : make_float4(0.f, 0.f, 0.f, 0.f);
            nB[i] = kv ? __ldg((const float4*)(Bg + (size_t)lrow * DD + k))
                       : make_float4(0.f, 0.f, 0.f, 0.f);
        }
    };

    auto convert_store = [&](int c) {
        char* st = sm + (c & 1) * STAGE;
        const int k0 = c * BK;
        #pragma unroll
        for (int g = 0; g < 2; g++) {
            const int kb = k0 + lhalf * 16 + g * 8;
            const uint32_t gg = ((uint32_t)(lhalf * 2 + g)) ^ lswz;
            // A: fold w3, accumulate rt with w1
            {
                float f[8];
                f[0] = nA[2 * g].x; f[1] = nA[2 * g].y; f[2] = nA[2 * g].z; f[3] = nA[2 * g].w;
                f[4] = nA[2 * g + 1].x; f[5] = nA[2 * g + 1].y;
                f[6] = nA[2 * g + 1].z; f[7] = nA[2 * g + 1].w;
                #pragma unroll
                for (int j = 0; j < 8; j++) {
                    rt_acc += f[j] * w1s[kb + j];
                    f[j] *= w3s[kb + j];
                }
                uint4 hi, lo;
                split8(f, hi, lo);
                *(uint4*)(st + OFF_AHI + lrow * ROWB + gg * 16) = hi;
                *(uint4*)(st + OFF_ALO + lrow * ROWB + gg * 16) = lo;
            }
            // B: accumulate ct with w2
            {
                float f[8];
                f[0] = nB[2 * g].x; f[1] = nB[2 * g].y; f[2] = nB[2 * g].z; f[3] = nB[2 * g].w;
                f[4] = nB[2 * g + 1].x; f[5] = nB[2 * g + 1].y;
                f[6] = nB[2 * g + 1].z; f[7] = nB[2 * g + 1].w;
                #pragma unroll
                for (int j = 0; j < 8; j++) ct_acc += f[j] * w2s[kb + j];
                uint4 hi, lo;
                split8(f, hi, lo);
                *(uint4*)(st + OFF_BHI + lrow * ROWB + gg * 16) = hi;
                *(uint4*)(st + OFF_BLO + lrow * ROWB + gg * 16) = lo;
            }
        }
    };

    // mma thread geometry: 2(M) x 4(N) warps, warp tile 64x32
    const int warpMoff = (w & 1) * 64;
    const int warpNoff = (w >> 1) * 32;
    const int lr  = lane & 15;
    const int lkg = lane >> 4;

    float acc[4][4][4];
    #pragma unroll
    for (int mf = 0; mf < 4; mf++)
        #pragma unroll
        for (int nf = 0; nf < 4; nf++)
            #pragma unroll
            for (int i = 0; i < 4; i++) acc[mf][nf][i] = 0.f;

    prefetch(0);
    convert_store(0);
    __syncthreads();

    for (int c = 0; c < NCH; c++) {
        if (c + 1 < NCH) prefetch(c + 1);

        // ---- MMA over chunk c ----
        {
            const uint32_t st = smu + (uint32_t)(c & 1) * STAGE;
            #pragma unroll
            for (int ks = 0; ks < 2; ks++) {
                uint32_t ah[4][4], al[4][4], bh[2][4], bl[2][4];
                #pragma unroll
                for (int mf = 0; mf < 4; mf++) {
                    const int row = warpMoff + mf * 16 + lr;
                    const uint32_t kg = ((uint32_t)(ks * 2 + lkg)) ^ ((((uint32_t)row >> 3) & 1u) << 1);
                    const uint32_t off = (uint32_t)row * ROWB + kg * 16;
                    ldsm_x4(ah[mf][0], ah[mf][1], ah[mf][2], ah[mf][3], st + OFF_AHI + off);
                    ldsm_x4(al[mf][0], al[mf][1], al[mf][2], al[mf][3], st + OFF_ALO + off);
                }
                #pragma unroll
                for (int j = 0; j < 2; j++) {
                    const int row = warpNoff + j * 16 + lr;
                    const uint32_t kg = ((uint32_t)(ks * 2 + lkg)) ^ ((((uint32_t)row >> 3) & 1u) << 1);
                    const uint32_t off = (uint32_t)row * ROWB + kg * 16;
                    ldsm_x4(bh[j][0], bh[j][1], bh[j][2], bh[j][3], st + OFF_BHI + off);
                    ldsm_x4(bl[j][0], bl[j][1], bl[j][2], bl[j][3], st + OFF_BLO + off);
                }
                #pragma unroll
                for (int mf = 0; mf < 4; mf++) {
                    #pragma unroll
                    for (int j = 0; j < 2; j++) {
                        mma_bf16(acc[mf][2 * j],     ah[mf], bh[j][0], bh[j][2]);
                        mma_bf16(acc[mf][2 * j],     ah[mf], bl[j][0], bl[j][2]);
                        mma_bf16(acc[mf][2 * j],     al[mf], bh[j][0], bh[j][2]);
                        mma_bf16(acc[mf][2 * j + 1], ah[mf], bh[j][1], bh[j][3]);
                        mma_bf16(acc[mf][2 * j + 1], ah[mf], bl[j][1], bl[j][3]);
                        mma_bf16(acc[mf][2 * j + 1], al[mf], bh[j][1], bh[j][3]);
                    }
                }
            }
        }

        if (c + 1 < NCH) convert_store(c + 1);
        __syncthreads();
    }

    // ---- reduce rank-1 terms (pairwise over lhalf lanes) ----
    {
        float r = rt_acc + __shfl_xor_sync(0xffffffffu, rt_acc, 1);
        float q = ct_acc + __shfl_xor_sync(0xffffffffu, ct_acc, 1);
        if (lhalf == 0) {
            rt_s[lrow] = r;
            ct_s[lrow] = q;
        }
    }
    __syncthreads();

    // ---- epilogue ----
    float* Cg = out + ((size_t)b * LC + rowTile) * LA + colTile;
    #pragma unroll
    for (int mf = 0; mf < 4; mf++) {
        const int r0 = warpMoff + mf * 16 + (lane >> 2);
        const int r1 = r0 + 8;
        const float rt0 = rt_s[r0], rt1 = rt_s[r1];
        #pragma unroll
        for (int nf = 0; nf < 4; nf++) {
            const int c0 = warpNoff + nf * 8 + (lane & 3) * 2;
            const float ct0 = ct_s[c0], ct1 = ct_s[c0 + 1];
            float2 v0 = make_float2(acc[mf][nf][0] + rt0 + ct0, acc[mf][nf][1] + rt0 + ct1);
            float2 v1 = make_float2(acc[mf][nf][2] + rt1 + ct0, acc[mf][nf][3] + rt1 + ct1);
            *(float2*)(Cg + (size_t)r0 * LA + c0) = v0;
            *(float2*)(Cg + (size_t)r1 * LA + c0) = v1;
        }
    }
}

extern "C" void kernel_launch(void* const* d_in, const int* in_sizes, int n_in,
                              void* d_out, int out_size)
{
    const float* ctx = nullptr;
    const float* asp = nullptr;
    const float* w_u = nullptr;
    for (int i = 0; i < n_in; i++) {
        if (in_sizes[i] == NB * LC * DD)      ctx = (const float*)d_in[i];
        else if (in_sizes[i] == NB * LA * DD) asp = (const float*)d_in[i];
        else if (in_sizes[i] == 3 * DD)       w_u = (const float*)d_in[i];
    }
    float* out = (float*)d_out;

    cudaFuncSetAttribute(alignment_hmma_kernel,
                         cudaFuncAttributeMaxDynamicSharedMemorySize, SMEM_TOTAL);

    dim3 grid(LA / BN, LC / BM, NB);   // (4, 16, 64)
    alignment_hmma_kernel<<<grid, 256, SMEM_TOTAL>>>(ctx, asp, w_u, out);

    (void)out_size;
}

// round 9
// speedup vs baseline: 2.0761x; 1.1924x over previous
#include <cuda_runtime.h>
#include <cuda_bf16.h>
#include <cstdint>

#define DD 400
#define LC 2048
#define LA 512
#define NB 64

#define BM 128
#define BN 128
#define BK 32
#define NCH 13            // ceil(400/32) -> K padded to 416
#define KPAD 416

// smem layout (bytes). bf16 tiles with 80B row stride (64B data + 16B pad).
// 20-bank row stride => any 8 consecutive rows hit distinct bank groups, so
// ldmatrix quarter-warp phases are conflict-free WITHOUT an xor swizzle.
#define ROWB 80
#define A_TILE (BM * ROWB)          // 10240
#define B_TILE (BN * ROWB)          // 10240
#define STAGE  (2 * A_TILE + 2 * B_TILE)   // 40960: Ahi, Alo, Bhi, Blo
#define OFF_AHI 0
#define OFF_ALO A_TILE
#define OFF_BHI (2 * A_TILE)
#define OFF_BLO (2 * A_TILE + B_TILE)
#define W_OFF   (2 * STAGE)                 // 81920
#define W_BYTES (KPAD * 4)                  // 1664 per vector
#define RT_OFF  (W_OFF + 3 * W_BYTES)       // 128 floats
#define CT_OFF  (RT_OFF + 512)              // 128 floats
#define SMEM_TOTAL (CT_OFF + 512)

__device__ __forceinline__ uint32_t smem_u32(const void* p) {
    uint32_t a;
    asm("{ .reg .u64 t; cvta.to.shared.u64 t, %1; cvt.u32.u64 %0, t; }" : "=r"(a) : "l"(p));
    return a;
}

__device__ __forceinline__ void ldsm_x4(uint32_t& r0, uint32_t& r1, uint32_t& r2, uint32_t& r3,
                                        uint32_t addr) {
    asm volatile("ldmatrix.sync.aligned.m8n8.x4.shared.b16 {%0,%1,%2,%3}, [%4];"
                 : "=r"(r0), "=r"(r1), "=r"(r2), "=r"(r3) : "r"(addr));
}

__device__ __forceinline__ void mma_bf16(float* d, const uint32_t* a, uint32_t b0, uint32_t b1) {
    asm volatile(
        "mma.sync.aligned.m16n8k16.row.col.f32.bf16.bf16.f32 "
        "{%0,%1,%2,%3}, {%4,%5,%6,%7}, {%8,%9}, {%0,%1,%2,%3};"
        : "+f"(d[0]), "+f"(d[1]), "+f"(d[2]), "+f"(d[3])
        : "r"(a[0]), "r"(a[1]), "r"(a[2]), "r"(a[3]), "r"(b0), "r"(b1));
}

__device__ __forceinline__ uint32_t packbf(float a, float b) {
    __nv_bfloat162 h = __floats2bfloat162_rn(a, b);
    return *reinterpret_cast<uint32_t*>(&h);
}

// split 8 floats into bf16 hi (uint4) and bf16 lo (uint4)
__device__ __forceinline__ void split8(const float* f, uint4& hi, uint4& lo) {
    float h[8], l[8];
    #pragma unroll
    for (int j = 0; j < 8; j++) {
        h[j] = __bfloat162float(__float2bfloat16(f[j]));
        l[j] = f[j] - h[j];
    }
    hi = make_uint4(packbf(h[0], h[1]), packbf(h[2], h[3]), packbf(h[4], h[5]), packbf(h[6], h[7]));
    lo = make_uint4(packbf(l[0], l[1]), packbf(l[2], l[3]), packbf(l[4], l[5]), packbf(l[6], l[7]));
}

__global__ __launch_bounds__(512, 1)
void alignment_hmma_kernel(const float* __restrict__ ctx,
                           const float* __restrict__ asp,
                           const float* __restrict__ w_u,
                           float* __restrict__ out)
{
    extern __shared__ char sm[];
    const uint32_t smu = smem_u32(sm);

    const int tid  = threadIdx.x;
    const int w    = tid >> 5;
    const int lane = tid & 31;
    const int b    = blockIdx.z;
    const int rowTile = blockIdx.y * BM;
    const int colTile = blockIdx.x * BN;

    const float* Ag = ctx + (size_t)b * LC * DD + (size_t)rowTile * DD;
    const float* Bg = asp + (size_t)b * LA * DD + (size_t)colTile * DD;

    float* w1s = (float*)(sm + W_OFF);
    float* w2s = (float*)(sm + W_OFF + W_BYTES);
    float* w3s = (float*)(sm + W_OFF + 2 * W_BYTES);
    float* rt_s = (float*)(sm + RT_OFF);
    float* ct_s = (float*)(sm + CT_OFF);

    for (int i = tid; i < KPAD; i += 512) {
        bool v = i < DD;
        w1s[i] = v ? w_u[i]          : 0.f;
        w2s[i] = v ? w_u[DD + i]     : 0.f;
        w3s[i] = v ? w_u[2 * DD + i] : 0.f;
    }
    __syncthreads();

    // loader roles: 512 threads; each owns one row-quarter (8 k-elems) of A and B
    const int lrow = tid >> 2;          // 0..127
    const int lq   = tid & 3;           // k-group (8 elems = 16B bf16)

    float rt_acc = 0.f, ct_acc = 0.f;

    float4 nA[2], nB[2];

    auto prefetch = [&](int c) {
        const int k0 = c * BK;
        #pragma unroll
        for (int i = 0; i < 2; i++) {
            int k = k0 + lq * 8 + i * 4;
            bool kv = k < DD;
            nA[i] = kv ? __ldg((const float4*)(Ag + (size_t)lrow * DD + k))
                       : make_float4(0.f, 0.f, 0.f, 0.f);
            nB[i] = kv ? __ldg((const float4*)(Bg + (size_t)lrow * DD + k))
                       : make_float4(0.f, 0.f, 0.f, 0.f);
        }
    };

    auto convert_store = [&](int c) {
        char* st = sm + (c & 1) * STAGE;
        const int kb = c * BK + lq * 8;
        // A: fold w3, accumulate rt with w1
        {
            float f[8];
            f[0] = nA[0].x; f[1] = nA[0].y; f[2] = nA[0].z; f[3] = nA[0].w;
            f[4] = nA[1].x; f[5] = nA[1].y; f[6] = nA[1].z; f[7] = nA[1].w;
            #pragma unroll
            for (int j = 0; j < 8; j++) {
                rt_acc += f[j] * w1s[kb + j];
                f[j] *= w3s[kb + j];
            }
            uint4 hi, lo;
            split8(f, hi, lo);
            *(uint4*)(st + OFF_AHI + lrow * ROWB + lq * 16) = hi;
            *(uint4*)(st + OFF_ALO + lrow * ROWB + lq * 16) = lo;
        }
        // B: accumulate ct with w2
        {
            float f[8];
            f[0] = nB[0].x; f[1] = nB[0].y; f[2] = nB[0].z; f[3] = nB[0].w;
            f[4] = nB[1].x; f[5] = nB[1].y; f[6] = nB[1].z; f[7] = nB[1].w;
            #pragma unroll
            for (int j = 0; j < 8; j++) ct_acc += f[j] * w2s[kb + j];
            uint4 hi, lo;
            split8(f, hi, lo);
            *(uint4*)(st + OFF_BHI + lrow * ROWB + lq * 16) = hi;
            *(uint4*)(st + OFF_BLO + lrow * ROWB + lq * 16) = lo;
        }
    };

    // mma thread geometry: 4(M) x 4(N) warps, warp tile 32x32
    const int warpMoff = (w & 3) * 32;
    const int warpNoff = (w >> 2) * 32;
    const int lr  = lane & 15;
    const int lkg = lane >> 4;

    float acc[2][4][4];
    #pragma unroll
    for (int mf = 0; mf < 2; mf++)
        #pragma unroll
        for (int nf = 0; nf < 4; nf++)
            #pragma unroll
            for (int i = 0; i < 4; i++) acc[mf][nf][i] = 0.f;

    prefetch(0);
    convert_store(0);
    __syncthreads();

    for (int c = 0; c < NCH; c++) {
        if (c + 1 < NCH) prefetch(c + 1);

        // ---- MMA over chunk c ----
        {
            const uint32_t st = smu + (uint32_t)(c & 1) * STAGE;
            #pragma unroll
            for (int ks = 0; ks < 2; ks++) {
                const uint32_t kg = (uint32_t)(ks * 2 + lkg);
                uint32_t ah[2][4], al[2][4], bh[2][4], bl[2][4];
                #pragma unroll
                for (int mf = 0; mf < 2; mf++) {
                    const int row = warpMoff + mf * 16 + lr;
                    const uint32_t off = (uint32_t)row * ROWB + kg * 16;
                    ldsm_x4(ah[mf][0], ah[mf][1], ah[mf][2], ah[mf][3], st + OFF_AHI + off);
                    ldsm_x4(al[mf][0], al[mf][1], al[mf][2], al[mf][3], st + OFF_ALO + off);
                }
                #pragma unroll
                for (int j = 0; j < 2; j++) {
                    const int row = warpNoff + j * 16 + lr;
                    const uint32_t off = (uint32_t)row * ROWB + kg * 16;
                    ldsm_x4(bh[j][0], bh[j][1], bh[j][2], bh[j][3], st + OFF_BHI + off);
                    ldsm_x4(bl[j][0], bl[j][1], bl[j][2], bl[j][3], st + OFF_BLO + off);
                }
                #pragma unroll
                for (int mf = 0; mf < 2; mf++) {
                    #pragma unroll
                    for (int j = 0; j < 2; j++) {
                        mma_bf16(acc[mf][2 * j],     ah[mf], bh[j][0], bh[j][2]);
                        mma_bf16(acc[mf][2 * j],     ah[mf], bl[j][0], bl[j][2]);
                        mma_bf16(acc[mf][2 * j],     al[mf], bh[j][0], bh[j][2]);
                        mma_bf16(acc[mf][2 * j + 1], ah[mf], bh[j][1], bh[j][3]);
                        mma_bf16(acc[mf][2 * j + 1], ah[mf], bl[j][1], bl[j][3]);
                        mma_bf16(acc[mf][2 * j + 1], al[mf], bh[j][1], bh[j][3]);
                    }
                }
            }
        }

        if (c + 1 < NCH) convert_store(c + 1);
        __syncthreads();
    }

    // ---- reduce rank-1 terms over the 4 lq lanes ----
    {
        float r = rt_acc, q = ct_acc;
        r += __shfl_xor_sync(0xffffffffu, r, 1);
        r += __shfl_xor_sync(0xffffffffu, r, 2);
        q += __shfl_xor_sync(0xffffffffu, q, 1);
        q += __shfl_xor_sync(0xffffffffu, q, 2);
        if (lq == 0) {
            rt_s[lrow] = r;
            ct_s[lrow] = q;
        }
    }
    __syncthreads();

    // ---- epilogue ----
    float* Cg = out + ((size_t)b * LC + rowTile) * LA + colTile;
    #pragma unroll
    for (int mf = 0; mf < 2; mf++) {
        const int r0 = warpMoff + mf * 16 + (lane >> 2);
        const int r1 = r0 + 8;
        const float rt0 = rt_s[r0], rt1 = rt_s[r1];
        #pragma unroll
        for (int nf = 0; nf < 4; nf++) {
            const int c0 = warpNoff + nf * 8 + (lane & 3) * 2;
            const float ct0 = ct_s[c0], ct1 = ct_s[c0 + 1];
            float2 v0 = make_float2(acc[mf][nf][0] + rt0 + ct0, acc[mf][nf][1] + rt0 + ct1);
            float2 v1 = make_float2(acc[mf][nf][2] + rt1 + ct0, acc[mf][nf][3] + rt1 + ct1);
            *(float2*)(Cg + (size_t)r0 * LA + c0) = v0;
            *(float2*)(Cg + (size_t)r1 * LA + c0) = v1;
        }
    }
}

extern "C" void kernel_launch(void* const* d_in, const int* in_sizes, int n_in,
                              void* d_out, int out_size)
{
    const float* ctx = nullptr;
    const float* asp = nullptr;
    const float* w_u = nullptr;
    for (int i = 0; i < n_in; i++) {
        if (in_sizes[i] == NB * LC * DD)      ctx = (const float*)d_in[i];
        else if (in_sizes[i] == NB * LA * DD) asp = (const float*)d_in[i];
        else if (in_sizes[i] == 3 * DD)       w_u = (const float*)d_in[i];
    }
    float* out = (float*)d_out;

    cudaFuncSetAttribute(alignment_hmma_kernel,
                         cudaFuncAttributeMaxDynamicSharedMemorySize, SMEM_TOTAL);

    dim3 grid(LA / BN, LC / BM, NB);   // (4, 16, 64)
    alignment_hmma_kernel<<<grid, 512, SMEM_TOTAL>>>(ctx, asp, w_u, out);

    (void)out_size;
}